// round 9
// baseline (speedup 1.0000x reference)
#include <cuda_runtime.h>
#include <cuda_fp16.h>
#include <cstdint>

#define T_TOTAL 2048
#define B_DIM   64
#define INP_DIM 512
#define OUT_DIM 512

#define NSEG    8
#define SEG_LEN 256                 // T per segment
#define MTILE   128                 // t rows per block tile
#define NSUB    (SEG_LEN / MTILE)   // 2
#define OTILE   128                 // o cols per block
#define KBLK    64                  // K per staged slice
#define NKBLK   (INP_DIM / KBLK)    // 8

typedef unsigned long long ull;
typedef unsigned int u32;

// ---- device scratch ----
__device__ float d_Aseg[NSEG * B_DIM * OUT_DIM];
__device__ float d_Bseg[NSEG * B_DIM * OUT_DIM];
// transposed fp16 weights: [o][k]
__device__ __half d_wg[OUT_DIM * INP_DIM];
__device__ __half d_wh[OUT_DIM * INP_DIM];

// ---- smem layout (bytes) ----
#define SOFF_BIAS 0                     // gb,hb,r,rb floats [4][128] = 2048
#define SOFF_QA   2048                  // [4][128] floats
#define SOFF_QB   4096
#define SOFF_STA  6144                  // [128] floats
#define SOFF_STB  6656
#define SOFF_BUF0 8192                  // two 48KB staging buffers
#define BUF_X     0                     // 128t x 64k fp16 = 16KB (SW128)
#define BUF_WG    16384                 // 128o x 64k fp16 = 16KB
#define BUF_WH    32768                 // 16KB
#define BUF_BYTES 49152
#define SOFF_GA   8192                  // alias: [64][128] float = 32KB (half-t G)
#define SOFF_GB   40960                 // alias: [64][128] float = 32KB (half-t H)
#define SMEM_BYTES (SOFF_BUF0 + 2 * BUF_BYTES)   // 106496

// ---- helpers ----
__device__ __forceinline__ u32 smem_u32(const void* p) {
    u32 a;
    asm("{ .reg .u64 t; cvta.to.shared.u64 t, %1; cvt.u32.u64 %0, t; }" : "=r"(a) : "l"(p));
    return a;
}
__device__ __forceinline__ void ldsm_x4(u32* r, u32 addr) {
    asm volatile("ldmatrix.sync.aligned.m8n8.x4.shared.b16 {%0,%1,%2,%3}, [%4];"
        : "=r"(r[0]), "=r"(r[1]), "=r"(r[2]), "=r"(r[3]) : "r"(addr));
}
__device__ __forceinline__ void mma16816(float* d, const u32* a, const u32* b) {
    asm volatile("mma.sync.aligned.m16n8k16.row.col.f32.f16.f16.f32 "
                 "{%0,%1,%2,%3}, {%4,%5,%6,%7}, {%8,%9}, {%0,%1,%2,%3};"
        : "+f"(d[0]), "+f"(d[1]), "+f"(d[2]), "+f"(d[3])
        : "r"(a[0]), "r"(a[1]), "r"(a[2]), "r"(a[3]), "r"(b[0]), "r"(b[1]));
}
__device__ __forceinline__ void cp_async16(u32 saddr, const void* gaddr) {
    asm volatile("cp.async.cg.shared.global [%0], [%1], 16;" :: "r"(saddr), "l"(gaddr));
}
#define CP_COMMIT()  asm volatile("cp.async.commit_group;" ::: "memory")
#define CP_WAIT0()   asm volatile("cp.async.wait_group 0;" ::: "memory")

__device__ __forceinline__ float sigf(float x)  { return 1.0f / (1.0f + __expf(-x)); }
__device__ __forceinline__ float tanhf_(float x){ return 2.0f / (1.0f + __expf(-2.0f * x)) - 1.0f; }

// ---------------- weight prep: tiled transpose fp32[k][o] -> fp16[o][k] ----------------
__global__ void wprep_kernel(const float* __restrict__ g, const float* __restrict__ h)
{
    __shared__ float tg[32][33], th[32][33];
    const int k0 = blockIdx.y * 32, o0 = blockIdx.x * 32;
    const int tx = threadIdx.x, ty = threadIdx.y;
    tg[ty][tx] = g[(size_t)(k0 + ty) * OUT_DIM + o0 + tx];
    th[ty][tx] = h[(size_t)(k0 + ty) * OUT_DIM + o0 + tx];
    __syncthreads();
    d_wg[(size_t)(o0 + ty) * INP_DIM + k0 + tx] = __float2half_rn(tg[tx][ty]);
    d_wh[(size_t)(o0 + ty) * INP_DIM + k0 + tx] = __float2half_rn(th[tx][ty]);
}

// ---------------- main fused kernel ----------------
// Grid: (4, 64, 8) = 2048 blocks, 512 threads (16 warps).
// Warp w: gate = w>>3 (0:G, 1:H), oq = (w>>2)&1 (64-o chunk), tq = w&3 (32-t chunk).
// Per-warp tile: 32t x 64o, one gate, fp16 mma m16n8k16.
__global__ __launch_bounds__(512)
void rnn_mma_kernel(const float* __restrict__ x,
                    const float* __restrict__ gb, const float* __restrict__ hb,
                    const float* __restrict__ r,  const float* __restrict__ rb)
{
    extern __shared__ char smem[];
    const u32 sb   = smem_u32(smem);
    const int tid  = threadIdx.x;
    const int lane = tid & 31;
    const int w    = tid >> 5;
    const int tq   = w & 3;
    const int oq   = (w >> 2) & 1;
    const int gate = w >> 3;
    const int s    = blockIdx.z;
    const int b    = blockIdx.y;
    const int o0   = blockIdx.x * OTILE;

    float* biasG  = (float*)(smem + SOFF_BIAS);
    float* biasH  = biasG + 128;
    float* biasR  = biasG + 256;
    float* biasRB = biasG + 384;
    float* qA     = (float*)(smem + SOFF_QA);
    float* qB     = (float*)(smem + SOFF_QB);
    float* stateA = (float*)(smem + SOFF_STA);
    float* stateB = (float*)(smem + SOFF_STB);

    if (tid < 128) {
        biasG[tid]  = gb[o0 + tid];
        biasH[tid]  = hb[o0 + tid];
        biasR[tid]  = r [o0 + tid];
        biasRB[tid] = rb[o0 + tid];
        stateA[tid] = 1.0f;
        stateB[tid] = 0.0f;
    }

    // ---- staging helpers ----
    // x: 128t x 64k = 2048 float4 chunks; 4 per thread, held in regs.
    auto ldg_x = [&](float4* xr, int t0, int k0) {
        #pragma unroll
        for (int it = 0; it < 4; it++) {
            int q  = tid + 512 * it;
            int m  = q >> 4;
            int f4 = q & 15;
            xr[it] = *(const float4*)&x[((size_t)(t0 + m) * B_DIM + b) * INP_DIM + k0 + f4 * 4];
        }
    };
    auto sts_x = [&](u32 bufoff, const float4* xr) {
        #pragma unroll
        for (int it = 0; it < 4; it++) {
            int q  = tid + 512 * it;
            int m  = q >> 4;
            int f4 = q & 15;
            __half2 p0 = __floats2half2_rn(xr[it].x, xr[it].y);
            __half2 p1 = __floats2half2_rn(xr[it].z, xr[it].w);
            u32 off = (u32)m * 128 + (u32)f4 * 8;
            u32 sw  = off ^ (((u32)(m & 7)) << 4);
            ull d = (ull)*(const u32*)&p0 | ((ull)*(const u32*)&p1 << 32);
            *(ull*)(smem + bufoff + BUF_X + sw) = d;
        }
    };
    auto stage_w = [&](u32 bufoff, int k0) {
        #pragma unroll
        for (int it = 0; it < 2; it++) {
            int q   = tid + 512 * it;        // 0..1023 16B chunks per gate
            int row = q >> 3;
            int u4  = q & 7;
            u32 off = (u32)row * 128 + (u32)u4 * 16;
            u32 sw  = off ^ (((u32)(row & 7)) << 4);
            const size_t gidx = (size_t)(o0 + row) * INP_DIM + k0 + u4 * 8;
            cp_async16(sb + bufoff + BUF_WG + sw, &d_wg[gidx]);
            cp_async16(sb + bufoff + BUF_WH + sw, &d_wh[gidx]);
        }
    };

    // ldmatrix per-lane address pieces
    const int rowA  = tq * 32 + (lane & 15);
    const u32 aXor  = ((u32)(rowA & 7)) << 4;
    const u32 aC0   = ((u32)(lane >> 4)) << 4;
    const int rowB0 = oq * 64 + (lane & 7) + ((lane >> 4) << 3);
    const u32 bC0   = ((u32)((lane >> 3) & 1)) << 4;
    const u32 wSel  = gate ? BUF_WH : BUF_WG;

    for (int sub = 0; sub < NSUB; sub++) {
        const int t0 = s * SEG_LEN + sub * MTILE;

        float acc[2][8][4];
        #pragma unroll
        for (int mt = 0; mt < 2; mt++)
            #pragma unroll
            for (int nt = 0; nt < 8; nt++)
                #pragma unroll
                for (int e = 0; e < 4; e++) acc[mt][nt][e] = 0.0f;

        // ---- prologue: stage k-block 0 into buf0 ----
        float4 xr[4];
        ldg_x(xr, t0, 0);
        stage_w(SOFF_BUF0, 0);
        CP_COMMIT();
        sts_x(SOFF_BUF0, xr);

        u32 buf = SOFF_BUF0;
        for (int kb = 0; kb < NKBLK; kb++) {
            const u32 nbuf = SOFF_BUF0 + (BUF_BYTES ^ (buf - SOFF_BUF0));
            const bool more = (kb + 1 < NKBLK);

            if (more) ldg_x(xr, t0, (kb + 1) * KBLK);   // overlap LDG with wait+compute
            CP_WAIT0();
            __syncthreads();              // buf staged & all warps past previous compute
            if (more) { stage_w(nbuf, (kb + 1) * KBLK); CP_COMMIT(); }

            // ---- compute: 4 k16 steps on `buf` ----
            const u32 aBase = sb + buf + BUF_X + (u32)rowA * 128;
            const u32 wBase = sb + buf + wSel;
            #pragma unroll
            for (int ks = 0; ks < 4; ks++) {
                u32 a[2][4];
                const u32 c = (aC0 + (u32)ks * 32) ^ aXor;
                ldsm_x4(a[0], aBase + c);
                ldsm_x4(a[1], aBase + 2048 + c);
                #pragma unroll
                for (int np = 0; np < 4; np++) {
                    const int rowB = rowB0 + np * 16;
                    const u32 boff = (u32)rowB * 128 + ((bC0 + (u32)ks * 32) ^ (((u32)(rowB & 7)) << 4));
                    u32 bf[4];
                    ldsm_x4(bf, wBase + boff);
                    #pragma unroll
                    for (int mt = 0; mt < 2; mt++) {
                        mma16816(acc[mt][np * 2 + 0], a[mt], bf + 0);
                        mma16816(acc[mt][np * 2 + 1], a[mt], bf + 2);
                    }
                }
            }
            if (more) sts_x(nbuf, xr);    // LDG data landed during compute
            buf = nbuf;
        }
        __syncthreads();                  // all compute done; GA/GB may alias buffers

        // ---- epilogue + scan, two 64-t halves ----
        #pragma unroll
        for (int half = 0; half < 2; half++) {
            if ((tq >> 1) == half) {
                float* dst = (float*)(smem + (gate ? SOFF_GB : SOFF_GA));
                #pragma unroll
                for (int mt = 0; mt < 2; mt++)
                    #pragma unroll
                    for (int nt = 0; nt < 8; nt++)
                        #pragma unroll
                        for (int e = 0; e < 4; e++) {
                            const int tl = (tq & 1) * 32 + mt * 16 + (lane >> 2) + ((e >> 1) * 8);
                            const int oo = oq * 64 + nt * 8 + (lane & 3) * 2 + (e & 1);
                            const float tn = (float)(t0 + half * 64 + tl) * (1.0f / (float)T_TOTAL);
                            const float rt = 2.0f * sigf(fmaf(tn, biasR[oo], biasRB[oo]));
                            const float v  = acc[mt][nt][e];
                            dst[tl * 128 + oo] = gate ? (tanhf_(v + biasH[oo]) * rt)
                                                      : (sigf (v + biasG[oo]) * rt);
                        }
            }
            __syncthreads();

            // quarter-spans of 16 t each, per o
            {
                const int oo = tid & 127, qt = tid >> 7;
                const float* GA = (const float*)(smem + SOFF_GA);
                const float* GB = (const float*)(smem + SOFF_GB);
                float A = 1.0f, Bv = 0.0f;
                #pragma unroll
                for (int i = 0; i < 16; i++) {
                    const int tl = qt * 16 + i;
                    const float a  = GA[tl * 128 + oo];
                    const float bb = GB[tl * 128 + oo];
                    Bv = fmaf(Bv, a, bb);
                    A *= a;
                }
                qA[qt * 128 + oo] = A;
                qB[qt * 128 + oo] = Bv;
            }
            __syncthreads();

            if (tid < 128) {
                float As = stateA[tid], Bs = stateB[tid];
                #pragma unroll
                for (int qt = 0; qt < 4; qt++) {
                    const float a  = qA[qt * 128 + tid];
                    const float bb = qB[qt * 128 + tid];
                    Bs = fmaf(Bs, a, bb);
                    As *= a;
                }
                stateA[tid] = As;
                stateB[tid] = Bs;
            }
            __syncthreads();   // state updated & GA/GB free before next half/sub staging
        }
    }

    if (tid < 128) {
        const size_t idx = ((size_t)s * B_DIM + b) * OUT_DIM + o0 + tid;
        d_Aseg[idx] = stateA[tid];
        d_Bseg[idx] = stateB[tid];
    }
}

// ---------------- final combine over segments ----------------
__global__ void rnn_combine_kernel(float* __restrict__ out)
{
    const int idx = blockIdx.x * blockDim.x + threadIdx.x;
    float y = 0.0f;
    #pragma unroll
    for (int s = 0; s < NSEG; s++) {
        const float A = d_Aseg[s * B_DIM * OUT_DIM + idx];
        const float B = d_Bseg[s * B_DIM * OUT_DIM + idx];
        y = fmaf(y, A, B);
    }
    out[idx] = y;
}

extern "C" void kernel_launch(void* const* d_in, const int* in_sizes, int n_in,
                              void* d_out, int out_size)
{
    const float* x  = (const float*)d_in[0];
    const float* g  = (const float*)d_in[1];
    const float* gb = (const float*)d_in[2];
    const float* h  = (const float*)d_in[3];
    const float* hb = (const float*)d_in[4];
    const float* r  = (const float*)d_in[5];
    const float* rb = (const float*)d_in[6];
    float* out = (float*)d_out;

    cudaFuncSetAttribute(rnn_mma_kernel, cudaFuncAttributeMaxDynamicSharedMemorySize, SMEM_BYTES);

    dim3 pgrid(OUT_DIM / 32, INP_DIM / 32);
    wprep_kernel<<<pgrid, dim3(32, 32)>>>(g, h);
    dim3 grid(OUT_DIM / OTILE, B_DIM, NSEG);   // (4, 64, 8)
    rnn_mma_kernel<<<grid, 512, SMEM_BYTES>>>(x, gb, hb, r, rb);
    rnn_combine_kernel<<<(B_DIM * OUT_DIM) / 512, 512>>>(out);
}

// round 10
// speedup vs baseline: 1.3543x; 1.3543x over previous
#include <cuda_runtime.h>
#include <cuda_fp16.h>
#include <cstdint>

#define T_TOTAL 2048
#define B_DIM   64
#define INP_DIM 512
#define OUT_DIM 512

#define NSEG    8
#define SEG_LEN 256                 // T per segment
#define MTILE   64                  // t rows per block tile
#define NSUB    (SEG_LEN / MTILE)   // 4
#define OTILE   128                 // o cols per block
#define KBLK    64                  // K per staged slice
#define NKBLK   (INP_DIM / KBLK)    // 8

typedef unsigned long long ull;
typedef unsigned int u32;

// ---- device scratch ----
__device__ float d_Aseg[NSEG * B_DIM * OUT_DIM];
__device__ float d_Bseg[NSEG * B_DIM * OUT_DIM];
// transposed fp16 weights: [o][k]
__device__ __half d_wg[OUT_DIM * INP_DIM];
__device__ __half d_wh[OUT_DIM * INP_DIM];

// ---- smem layout (bytes) ----
#define SOFF_BIAS 0                     // gb,hb,r,rb floats [4][128] = 2048
#define SOFF_QA   2048                  // [4][128] floats
#define SOFF_QB   4096
#define SOFF_STA  6144                  // [128] floats
#define SOFF_STB  6656
#define SOFF_BUF0 8192                  // two 40KB staging buffers
#define BUF_X     0                     // 64t x 64k fp16 = 8KB (SW128)
#define BUF_WG    8192                  // 128o x 64k fp16 = 16KB
#define BUF_WH    24576                 // 16KB
#define BUF_BYTES 40960
#define SOFF_GA   8192                  // alias: [64][128] float = 32KB (G gate)
#define SOFF_GB   40960                 // alias: [64][128] float = 32KB (H gate)
#define SMEM_BYTES (SOFF_BUF0 + 2 * BUF_BYTES)   // 90112

// ---- helpers ----
__device__ __forceinline__ u32 smem_u32(const void* p) {
    u32 a;
    asm("{ .reg .u64 t; cvta.to.shared.u64 t, %1; cvt.u32.u64 %0, t; }" : "=r"(a) : "l"(p));
    return a;
}
__device__ __forceinline__ void ldsm_x4(u32* r, u32 addr) {
    asm volatile("ldmatrix.sync.aligned.m8n8.x4.shared.b16 {%0,%1,%2,%3}, [%4];"
        : "=r"(r[0]), "=r"(r[1]), "=r"(r[2]), "=r"(r[3]) : "r"(addr));
}
__device__ __forceinline__ void mma16816(float* d, const u32* a, const u32* b) {
    asm volatile("mma.sync.aligned.m16n8k16.row.col.f32.f16.f16.f32 "
                 "{%0,%1,%2,%3}, {%4,%5,%6,%7}, {%8,%9}, {%0,%1,%2,%3};"
        : "+f"(d[0]), "+f"(d[1]), "+f"(d[2]), "+f"(d[3])
        : "r"(a[0]), "r"(a[1]), "r"(a[2]), "r"(a[3]), "r"(b[0]), "r"(b[1]));
}
__device__ __forceinline__ void cp_async16(u32 saddr, const void* gaddr) {
    asm volatile("cp.async.cg.shared.global [%0], [%1], 16;" :: "r"(saddr), "l"(gaddr));
}
#define CP_COMMIT()  asm volatile("cp.async.commit_group;" ::: "memory")
#define CP_WAIT0()   asm volatile("cp.async.wait_group 0;" ::: "memory")

__device__ __forceinline__ float sigf(float x)  { return 1.0f / (1.0f + __expf(-x)); }
__device__ __forceinline__ float tanhf_(float x){ return 2.0f / (1.0f + __expf(-2.0f * x)) - 1.0f; }

// ---------------- weight prep: tiled transpose fp32[k][o] -> fp16[o][k] ----------------
__global__ void wprep_kernel(const float* __restrict__ g, const float* __restrict__ h)
{
    __shared__ float tg[32][33], th[32][33];
    const int k0 = blockIdx.y * 32, o0 = blockIdx.x * 32;
    const int tx = threadIdx.x, ty = threadIdx.y;
    tg[ty][tx] = g[(size_t)(k0 + ty) * OUT_DIM + o0 + tx];
    th[ty][tx] = h[(size_t)(k0 + ty) * OUT_DIM + o0 + tx];
    __syncthreads();
    d_wg[(size_t)(o0 + ty) * INP_DIM + k0 + tx] = __float2half_rn(tg[tx][ty]);
    d_wh[(size_t)(o0 + ty) * INP_DIM + k0 + tx] = __float2half_rn(th[tx][ty]);
}

// ---------------- main fused kernel ----------------
// Grid: (4, 64, 8) = 2048 blocks, 512 threads (16 warps).
// Warp w: gate = w>>3 (0:G, 1:H), tq = (w>>2)&1 (32-t chunk), oq = w&3 (32-o chunk).
// Per-warp tile: 32t x 32o, one gate, fp16 mma m16n8k16.
__global__ __launch_bounds__(512)
void rnn_mma_kernel(const float* __restrict__ x,
                    const float* __restrict__ gb, const float* __restrict__ hb,
                    const float* __restrict__ r,  const float* __restrict__ rb)
{
    extern __shared__ char smem[];
    const u32 sb   = smem_u32(smem);
    const int tid  = threadIdx.x;
    const int lane = tid & 31;
    const int w    = tid >> 5;
    const int oq   = w & 3;
    const int tq   = (w >> 2) & 1;
    const int gate = w >> 3;
    const int s    = blockIdx.z;
    const int b    = blockIdx.y;
    const int o0   = blockIdx.x * OTILE;

    float* biasG  = (float*)(smem + SOFF_BIAS);
    float* biasH  = biasG + 128;
    float* biasR  = biasG + 256;
    float* biasRB = biasG + 384;
    float* qA     = (float*)(smem + SOFF_QA);
    float* qB     = (float*)(smem + SOFF_QB);
    float* stateA = (float*)(smem + SOFF_STA);
    float* stateB = (float*)(smem + SOFF_STB);

    if (tid < 128) {
        biasG[tid]  = gb[o0 + tid];
        biasH[tid]  = hb[o0 + tid];
        biasR[tid]  = r [o0 + tid];
        biasRB[tid] = rb[o0 + tid];
        stateA[tid] = 1.0f;
        stateB[tid] = 0.0f;
    }

    // ---- staging helpers ----
    // x: 64t x 64k = 1024 float4 chunks; 2 per thread, held in regs across compute.
    auto ldg_x = [&](float4* xr, int t0, int k0) {
        #pragma unroll
        for (int it = 0; it < 2; it++) {
            int q  = tid + 512 * it;
            int m  = q >> 4;
            int f4 = q & 15;
            xr[it] = *(const float4*)&x[((size_t)(t0 + m) * B_DIM + b) * INP_DIM + k0 + f4 * 4];
        }
    };
    auto sts_x = [&](u32 bufoff, const float4* xr) {
        #pragma unroll
        for (int it = 0; it < 2; it++) {
            int q  = tid + 512 * it;
            int m  = q >> 4;
            int f4 = q & 15;
            __half2 p0 = __floats2half2_rn(xr[it].x, xr[it].y);
            __half2 p1 = __floats2half2_rn(xr[it].z, xr[it].w);
            u32 off = (u32)m * 128 + (u32)f4 * 8;
            u32 sw  = off ^ (((u32)(m & 7)) << 4);
            ull d = (ull)*(const u32*)&p0 | ((ull)*(const u32*)&p1 << 32);
            *(ull*)(smem + bufoff + BUF_X + sw) = d;
        }
    };
    auto stage_w = [&](u32 bufoff, int k0) {
        #pragma unroll
        for (int it = 0; it < 2; it++) {
            int q   = tid + 512 * it;        // 0..1023 16B chunks per gate
            int row = q >> 3;
            int u4  = q & 7;
            u32 off = (u32)row * 128 + (u32)u4 * 16;
            u32 sw  = off ^ (((u32)(row & 7)) << 4);
            const size_t gidx = (size_t)(o0 + row) * INP_DIM + k0 + u4 * 8;
            cp_async16(sb + bufoff + BUF_WG + sw, &d_wg[gidx]);
            cp_async16(sb + bufoff + BUF_WH + sw, &d_wh[gidx]);
        }
    };

    // ldmatrix per-lane address pieces
    const int rowA  = tq * 32 + (lane & 15);
    const u32 aXor  = ((u32)(rowA & 7)) << 4;
    const u32 aC0   = ((u32)(lane >> 4)) << 4;
    const int rowB0 = oq * 32 + (lane & 7) + ((lane >> 4) << 3);   // x4: two n8 tiles
    const u32 bC0   = ((u32)((lane >> 3) & 1)) << 4;
    const u32 wSel  = gate ? BUF_WH : BUF_WG;

    for (int sub = 0; sub < NSUB; sub++) {
        const int t0 = s * SEG_LEN + sub * MTILE;

        float acc[2][4][4];
        #pragma unroll
        for (int mt = 0; mt < 2; mt++)
            #pragma unroll
            for (int nt = 0; nt < 4; nt++)
                #pragma unroll
                for (int e = 0; e < 4; e++) acc[mt][nt][e] = 0.0f;

        // ---- prologue: stage k-block 0 into buf0 ----
        float4 xr[2];
        ldg_x(xr, t0, 0);
        stage_w(SOFF_BUF0, 0);
        CP_COMMIT();
        sts_x(SOFF_BUF0, xr);

        u32 buf = SOFF_BUF0;
        for (int kb = 0; kb < NKBLK; kb++) {
            const u32 nbuf = SOFF_BUF0 + (BUF_BYTES ^ (buf - SOFF_BUF0));
            const bool more = (kb + 1 < NKBLK);

            if (more) ldg_x(xr, t0, (kb + 1) * KBLK);   // LDG rides under wait+compute
            CP_WAIT0();
            __syncthreads();              // buf fully staged; prior compute done
            if (more) { stage_w(nbuf, (kb + 1) * KBLK); CP_COMMIT(); }  // overlaps mmas

            // ---- compute: 4 k16 steps on `buf` ----
            const u32 aBase = sb + buf + BUF_X + (u32)rowA * 128;
            const u32 wBase = sb + buf + wSel;
            #pragma unroll
            for (int ks = 0; ks < 4; ks++) {
                u32 a[2][4];
                const u32 c = (aC0 + (u32)ks * 32) ^ aXor;
                ldsm_x4(a[0], aBase + c);
                ldsm_x4(a[1], aBase + 2048 + c);
                #pragma unroll
                for (int np = 0; np < 2; np++) {
                    const int rowB = rowB0 + np * 16;
                    const u32 boff = (u32)rowB * 128 + ((bC0 + (u32)ks * 32) ^ (((u32)(rowB & 7)) << 4));
                    u32 bf[4];
                    ldsm_x4(bf, wBase + boff);      // two n8 tiles
                    #pragma unroll
                    for (int mt = 0; mt < 2; mt++) {
                        mma16816(acc[mt][np * 2 + 0], a[mt], bf + 0);
                        mma16816(acc[mt][np * 2 + 1], a[mt], bf + 2);
                    }
                }
            }
            if (more) sts_x(nbuf, xr);    // LDG data has landed during compute
            buf = nbuf;
        }
        __syncthreads();                  // all compute done; GA/GB may alias buffers

        // ---- epilogue: activations at mma layout -> smem [64t][128o] ----
        {
            float* dst = (float*)(smem + (gate ? SOFF_GB : SOFF_GA));
            #pragma unroll
            for (int mt = 0; mt < 2; mt++)
                #pragma unroll
                for (int np = 0; np < 2; np++)
                    #pragma unroll
                    for (int j = 0; j < 2; j++)
                        #pragma unroll
                        for (int e = 0; e < 4; e++) {
                            const int tl = tq * 32 + mt * 16 + (lane >> 2) + ((e >> 1) * 8);
                            const int oo = oq * 32 + np * 16 + j * 8 + (lane & 3) * 2 + (e & 1);
                            const float tn = (float)(t0 + tl) * (1.0f / (float)T_TOTAL);
                            const float rt = 2.0f * sigf(fmaf(tn, biasR[oo], biasRB[oo]));
                            const float v  = acc[mt][np * 2 + j][e];
                            dst[tl * 128 + oo] = gate ? (tanhf_(v + biasH[oo]) * rt)
                                                      : (sigf (v + biasG[oo]) * rt);
                        }
        }
        __syncthreads();

        // ---- scan: 4 quarter-spans of 16 t each, per o ----
        {
            const int oo = tid & 127, qt = tid >> 7;
            const float* GA = (const float*)(smem + SOFF_GA);
            const float* GB = (const float*)(smem + SOFF_GB);
            float A = 1.0f, Bv = 0.0f;
            #pragma unroll
            for (int i = 0; i < 16; i++) {
                const int tl = qt * 16 + i;
                const float a  = GA[tl * 128 + oo];
                const float bb = GB[tl * 128 + oo];
                Bv = fmaf(Bv, a, bb);
                A *= a;
            }
            qA[qt * 128 + oo] = A;
            qB[qt * 128 + oo] = Bv;
        }
        __syncthreads();

        if (tid < 128) {
            float As = stateA[tid], Bs = stateB[tid];
            #pragma unroll
            for (int qt = 0; qt < 4; qt++) {
                const float a  = qA[qt * 128 + tid];
                const float bb = qB[qt * 128 + tid];
                Bs = fmaf(Bs, a, bb);
                As *= a;
            }
            stateA[tid] = As;
            stateB[tid] = Bs;
        }
        __syncthreads();   // state/scan reads done before next sub's staging overwrites
    }

    if (tid < 128) {
        const size_t idx = ((size_t)s * B_DIM + b) * OUT_DIM + o0 + tid;
        d_Aseg[idx] = stateA[tid];
        d_Bseg[idx] = stateB[tid];
    }
}

// ---------------- final combine over segments ----------------
__global__ void rnn_combine_kernel(float* __restrict__ out)
{
    const int idx = blockIdx.x * blockDim.x + threadIdx.x;
    float y = 0.0f;
    #pragma unroll
    for (int s = 0; s < NSEG; s++) {
        const float A = d_Aseg[s * B_DIM * OUT_DIM + idx];
        const float B = d_Bseg[s * B_DIM * OUT_DIM + idx];
        y = fmaf(y, A, B);
    }
    out[idx] = y;
}

extern "C" void kernel_launch(void* const* d_in, const int* in_sizes, int n_in,
                              void* d_out, int out_size)
{
    const float* x  = (const float*)d_in[0];
    const float* g  = (const float*)d_in[1];
    const float* gb = (const float*)d_in[2];
    const float* h  = (const float*)d_in[3];
    const float* hb = (const float*)d_in[4];
    const float* r  = (const float*)d_in[5];
    const float* rb = (const float*)d_in[6];
    float* out = (float*)d_out;

    cudaFuncSetAttribute(rnn_mma_kernel, cudaFuncAttributeMaxDynamicSharedMemorySize, SMEM_BYTES);

    dim3 pgrid(OUT_DIM / 32, INP_DIM / 32);
    wprep_kernel<<<pgrid, dim3(32, 32)>>>(g, h);
    dim3 grid(OUT_DIM / OTILE, B_DIM, NSEG);   // (4, 64, 8)
    rnn_mma_kernel<<<grid, 512, SMEM_BYTES>>>(x, gb, hb, r, rb);
    rnn_combine_kernel<<<(B_DIM * OUT_DIM) / 512, 512>>>(out);
}

// round 11
// speedup vs baseline: 1.6996x; 1.2549x over previous
#include <cuda_runtime.h>
#include <cuda_fp16.h>
#include <cstdint>

#define T_TOTAL 2048
#define B_DIM   64
#define INP_DIM 512
#define OUT_DIM 512

#define NSEG    8
#define SEG_LEN 256                 // T per segment
#define MTILE   64                  // t rows per block tile
#define NSUB    (SEG_LEN / MTILE)   // 4
#define OTILE   128                 // o cols per block
#define KBLK    64                  // K per staged slice
#define NKBLK   (INP_DIM / KBLK)    // 8

typedef unsigned long long ull;
typedef unsigned int u32;

// ---- device scratch ----
__device__ float d_Aseg[NSEG * B_DIM * OUT_DIM];
__device__ float d_Bseg[NSEG * B_DIM * OUT_DIM];
// transposed fp16 weights: [o][k]
__device__ __half d_wg[OUT_DIM * INP_DIM];
__device__ __half d_wh[OUT_DIM * INP_DIM];

// ---- smem layout (bytes) ----
#define SOFF_BIAS 0                     // gb,hb,r,rb floats [4][128] = 2048
#define SOFF_QA   2048                  // [2][128] floats
#define SOFF_QB   3072
#define SOFF_STA  4096                  // [128] floats
#define SOFF_STB  4608
#define SOFF_BUF0 8192                  // two 40KB staging buffers
#define BUF_X     0                     // 64t x 64k fp16 = 8KB (SW128)
#define BUF_WG    8192                  // 128o x 64k fp16 = 16KB
#define BUF_WH    24576                 // 16KB
#define BUF_BYTES 40960
#define SOFF_GA   8192                  // alias: [64][128] float = 32KB (G gate)
#define SOFF_GB   40960                 // alias: [64][128] float = 32KB (H gate)
#define SMEM_BYTES (SOFF_BUF0 + 2 * BUF_BYTES)   // 90112  (x2 CTAs = 176KB/SM)

// ---- helpers ----
__device__ __forceinline__ u32 smem_u32(const void* p) {
    u32 a;
    asm("{ .reg .u64 t; cvta.to.shared.u64 t, %1; cvt.u32.u64 %0, t; }" : "=r"(a) : "l"(p));
    return a;
}
__device__ __forceinline__ void ldsm_x4(u32* r, u32 addr) {
    asm volatile("ldmatrix.sync.aligned.m8n8.x4.shared.b16 {%0,%1,%2,%3}, [%4];"
        : "=r"(r[0]), "=r"(r[1]), "=r"(r[2]), "=r"(r[3]) : "r"(addr));
}
__device__ __forceinline__ void mma16816(float* d, const u32* a, const u32* b) {
    asm volatile("mma.sync.aligned.m16n8k16.row.col.f32.f16.f16.f32 "
                 "{%0,%1,%2,%3}, {%4,%5,%6,%7}, {%8,%9}, {%0,%1,%2,%3};"
        : "+f"(d[0]), "+f"(d[1]), "+f"(d[2]), "+f"(d[3])
        : "r"(a[0]), "r"(a[1]), "r"(a[2]), "r"(a[3]), "r"(b[0]), "r"(b[1]));
}
__device__ __forceinline__ void cp_async16(u32 saddr, const void* gaddr) {
    asm volatile("cp.async.cg.shared.global [%0], [%1], 16;" :: "r"(saddr), "l"(gaddr));
}
#define CP_COMMIT()  asm volatile("cp.async.commit_group;" ::: "memory")
#define CP_WAIT0()   asm volatile("cp.async.wait_group 0;" ::: "memory")

__device__ __forceinline__ float sigf(float x)  { return 1.0f / (1.0f + __expf(-x)); }
__device__ __forceinline__ float tanhf_(float x){ return 2.0f / (1.0f + __expf(-2.0f * x)) - 1.0f; }

// ---------------- weight prep: tiled transpose fp32[k][o] -> fp16[o][k] ----------------
__global__ void wprep_kernel(const float* __restrict__ g, const float* __restrict__ h)
{
    __shared__ float tg[32][33], th[32][33];
    const int k0 = blockIdx.y * 32, o0 = blockIdx.x * 32;
    const int tx = threadIdx.x, ty = threadIdx.y;
    tg[ty][tx] = g[(size_t)(k0 + ty) * OUT_DIM + o0 + tx];
    th[ty][tx] = h[(size_t)(k0 + ty) * OUT_DIM + o0 + tx];
    __syncthreads();
    d_wg[(size_t)(o0 + ty) * INP_DIM + k0 + tx] = __float2half_rn(tg[tx][ty]);
    d_wh[(size_t)(o0 + ty) * INP_DIM + k0 + tx] = __float2half_rn(th[tx][ty]);
}

// ---------------- main fused kernel ----------------
// Grid: (4, 64, 8) = 2048 blocks, 256 threads (8 warps), 2 CTAs/SM.
// Warp w: gate = w>>2 (0:G, 1:H), oq = w&3 (32-o chunk).
// Per-warp tile: 64t x 32o, one gate, fp16 mma m16n8k16 (acc 4mt x 4nt x 4).
__global__ __launch_bounds__(256, 2)
void rnn_mma_kernel(const float* __restrict__ x,
                    const float* __restrict__ gb, const float* __restrict__ hb,
                    const float* __restrict__ r,  const float* __restrict__ rb)
{
    extern __shared__ char smem[];
    const u32 sb   = smem_u32(smem);
    const int tid  = threadIdx.x;
    const int lane = tid & 31;
    const int w    = tid >> 5;
    const int oq   = w & 3;
    const int gate = w >> 2;
    const int s    = blockIdx.z;
    const int b    = blockIdx.y;
    const int o0   = blockIdx.x * OTILE;

    float* biasG  = (float*)(smem + SOFF_BIAS);
    float* biasH  = biasG + 128;
    float* biasR  = biasG + 256;
    float* biasRB = biasG + 384;
    float* qA     = (float*)(smem + SOFF_QA);
    float* qB     = (float*)(smem + SOFF_QB);
    float* stateA = (float*)(smem + SOFF_STA);
    float* stateB = (float*)(smem + SOFF_STB);

    if (tid < 128) {
        biasG[tid]  = gb[o0 + tid];
        biasH[tid]  = hb[o0 + tid];
        biasR[tid]  = r [o0 + tid];
        biasRB[tid] = rb[o0 + tid];
        stateA[tid] = 1.0f;
        stateB[tid] = 0.0f;
    }

    // ---- staging helpers ----
    // x: 64t x 64k = 1024 float4 chunks; 4 per thread, held in regs across compute.
    auto ldg_x = [&](float4* xr, int t0, int k0) {
        #pragma unroll
        for (int it = 0; it < 4; it++) {
            int q  = tid + 256 * it;
            int m  = q >> 4;
            int f4 = q & 15;
            xr[it] = *(const float4*)&x[((size_t)(t0 + m) * B_DIM + b) * INP_DIM + k0 + f4 * 4];
        }
    };
    auto sts_x = [&](u32 bufoff, const float4* xr) {
        #pragma unroll
        for (int it = 0; it < 4; it++) {
            int q  = tid + 256 * it;
            int m  = q >> 4;
            int f4 = q & 15;
            __half2 p0 = __floats2half2_rn(xr[it].x, xr[it].y);
            __half2 p1 = __floats2half2_rn(xr[it].z, xr[it].w);
            u32 off = (u32)m * 128 + (u32)f4 * 8;
            u32 sw  = off ^ (((u32)(m & 7)) << 4);
            ull d = (ull)*(const u32*)&p0 | ((ull)*(const u32*)&p1 << 32);
            *(ull*)(smem + bufoff + BUF_X + sw) = d;
        }
    };
    auto stage_w = [&](u32 bufoff, int k0) {
        #pragma unroll
        for (int it = 0; it < 4; it++) {
            int q   = tid + 256 * it;        // 0..1023 16B chunks per gate
            int row = q >> 3;
            int u4  = q & 7;
            u32 off = (u32)row * 128 + (u32)u4 * 16;
            u32 sw  = off ^ (((u32)(row & 7)) << 4);
            const size_t gidx = (size_t)(o0 + row) * INP_DIM + k0 + u4 * 8;
            cp_async16(sb + bufoff + BUF_WG + sw, &d_wg[gidx]);
            cp_async16(sb + bufoff + BUF_WH + sw, &d_wh[gidx]);
        }
    };

    // ldmatrix per-lane address pieces
    const int rowA  = lane & 15;                                   // + mt*16
    const u32 aXor  = ((u32)(rowA & 7)) << 4;
    const u32 aC0   = ((u32)(lane >> 4)) << 4;
    const int rowB0 = oq * 32 + (lane & 7) + ((lane >> 4) << 3);   // x4: two n8 tiles
    const u32 bC0   = ((u32)((lane >> 3) & 1)) << 4;
    const u32 wSel  = gate ? BUF_WH : BUF_WG;

    for (int sub = 0; sub < NSUB; sub++) {
        const int t0 = s * SEG_LEN + sub * MTILE;

        float acc[4][4][4];
        #pragma unroll
        for (int mt = 0; mt < 4; mt++)
            #pragma unroll
            for (int nt = 0; nt < 4; nt++)
                #pragma unroll
                for (int e = 0; e < 4; e++) acc[mt][nt][e] = 0.0f;

        // ---- prologue: stage k-block 0 into buf0 ----
        float4 xr[4];
        ldg_x(xr, t0, 0);
        stage_w(SOFF_BUF0, 0);
        CP_COMMIT();
        sts_x(SOFF_BUF0, xr);

        u32 buf = SOFF_BUF0;
        for (int kb = 0; kb < NKBLK; kb++) {
            const u32 nbuf = SOFF_BUF0 + (BUF_BYTES ^ (buf - SOFF_BUF0));
            const bool more = (kb + 1 < NKBLK);

            if (more) ldg_x(xr, t0, (kb + 1) * KBLK);   // LDG rides under wait+compute
            CP_WAIT0();
            __syncthreads();              // buf fully staged; prior compute done
            if (more) { stage_w(nbuf, (kb + 1) * KBLK); CP_COMMIT(); }  // overlaps mmas

            // ---- compute: 4 k16 steps on `buf` ----
            const u32 aBase = sb + buf + BUF_X + (u32)rowA * 128;
            const u32 wBase = sb + buf + wSel;
            #pragma unroll
            for (int ks = 0; ks < 4; ks++) {
                u32 a[4][4];
                const u32 c = (aC0 + (u32)ks * 32) ^ aXor;
                #pragma unroll
                for (int mt = 0; mt < 4; mt++)
                    ldsm_x4(a[mt], aBase + (u32)mt * 2048 + c);
                #pragma unroll
                for (int np = 0; np < 2; np++) {
                    const int rowB = rowB0 + np * 16;
                    const u32 boff = (u32)rowB * 128 + ((bC0 + (u32)ks * 32) ^ (((u32)(rowB & 7)) << 4));
                    u32 bf[4];
                    ldsm_x4(bf, wBase + boff);      // two n8 tiles
                    #pragma unroll
                    for (int mt = 0; mt < 4; mt++) {
                        mma16816(acc[mt][np * 2 + 0], a[mt], bf + 0);
                        mma16816(acc[mt][np * 2 + 1], a[mt], bf + 2);
                    }
                }
            }
            if (more) sts_x(nbuf, xr);    // LDG data has landed during compute
            buf = nbuf;
        }
        __syncthreads();                  // all compute done; GA/GB may alias buffers

        // ---- epilogue: activations at mma layout -> smem [64t][128o] ----
        {
            float* dst = (float*)(smem + (gate ? SOFF_GB : SOFF_GA));
            #pragma unroll
            for (int mt = 0; mt < 4; mt++)
                #pragma unroll
                for (int np = 0; np < 2; np++)
                    #pragma unroll
                    for (int j = 0; j < 2; j++)
                        #pragma unroll
                        for (int e = 0; e < 4; e++) {
                            const int tl = mt * 16 + (lane >> 2) + ((e >> 1) * 8);
                            const int oo = oq * 32 + np * 16 + j * 8 + (lane & 3) * 2 + (e & 1);
                            const float tn = (float)(t0 + tl) * (1.0f / (float)T_TOTAL);
                            const float rt = 2.0f * sigf(fmaf(tn, biasR[oo], biasRB[oo]));
                            const float v  = acc[mt][np * 2 + j][e];
                            dst[tl * 128 + oo] = gate ? (tanhf_(v + biasH[oo]) * rt)
                                                      : (sigf (v + biasG[oo]) * rt);
                        }
        }
        __syncthreads();

        // ---- scan: 2 half-spans of 32 t each, per o ----
        {
            const int oo = tid & 127, qt = tid >> 7;   // qt in {0,1}
            const float* GA = (const float*)(smem + SOFF_GA);
            const float* GB = (const float*)(smem + SOFF_GB);
            float A = 1.0f, Bv = 0.0f;
            #pragma unroll
            for (int i = 0; i < 32; i++) {
                const int tl = qt * 32 + i;
                const float a  = GA[tl * 128 + oo];
                const float bb = GB[tl * 128 + oo];
                Bv = fmaf(Bv, a, bb);
                A *= a;
            }
            qA[qt * 128 + oo] = A;
            qB[qt * 128 + oo] = Bv;
        }
        __syncthreads();

        if (tid < 128) {
            float As = stateA[tid], Bs = stateB[tid];
            #pragma unroll
            for (int qt = 0; qt < 2; qt++) {
                const float a  = qA[qt * 128 + tid];
                const float bb = qB[qt * 128 + tid];
                Bs = fmaf(Bs, a, bb);
                As *= a;
            }
            stateA[tid] = As;
            stateB[tid] = Bs;
        }
        __syncthreads();   // state/scan reads done before next sub's staging overwrites
    }

    if (tid < 128) {
        const size_t idx = ((size_t)s * B_DIM + b) * OUT_DIM + o0 + tid;
        d_Aseg[idx] = stateA[tid];
        d_Bseg[idx] = stateB[tid];
    }
}

// ---------------- final combine over segments ----------------
__global__ void rnn_combine_kernel(float* __restrict__ out)
{
    const int idx = blockIdx.x * blockDim.x + threadIdx.x;
    float y = 0.0f;
    #pragma unroll
    for (int s = 0; s < NSEG; s++) {
        const float A = d_Aseg[s * B_DIM * OUT_DIM + idx];
        const float B = d_Bseg[s * B_DIM * OUT_DIM + idx];
        y = fmaf(y, A, B);
    }
    out[idx] = y;
}

extern "C" void kernel_launch(void* const* d_in, const int* in_sizes, int n_in,
                              void* d_out, int out_size)
{
    const float* x  = (const float*)d_in[0];
    const float* g  = (const float*)d_in[1];
    const float* gb = (const float*)d_in[2];
    const float* h  = (const float*)d_in[3];
    const float* hb = (const float*)d_in[4];
    const float* r  = (const float*)d_in[5];
    const float* rb = (const float*)d_in[6];
    float* out = (float*)d_out;

    cudaFuncSetAttribute(rnn_mma_kernel, cudaFuncAttributeMaxDynamicSharedMemorySize, SMEM_BYTES);

    dim3 pgrid(OUT_DIM / 32, INP_DIM / 32);
    wprep_kernel<<<pgrid, dim3(32, 32)>>>(g, h);
    dim3 grid(OUT_DIM / OTILE, B_DIM, NSEG);   // (4, 64, 8)
    rnn_mma_kernel<<<grid, 256, SMEM_BYTES>>>(x, gb, hb, r, rb);
    rnn_combine_kernel<<<(B_DIM * OUT_DIM) / 512, 512>>>(out);
}

// round 14
// speedup vs baseline: 1.7705x; 1.0417x over previous
#include <cuda_runtime.h>
#include <cuda_fp16.h>
#include <cstdint>

#define T_TOTAL 2048
#define B_DIM   64
#define INP_DIM 512
#define OUT_DIM 512

#define NSEG    8
#define SEG_LEN 256                 // T per segment
#define MTILE   64                  // t rows per block tile
#define NSUB    (SEG_LEN / MTILE)   // 4
#define OTILE   128                 // o cols per block
#define KBLK    64                  // K per staged slice
#define NKBLK   (INP_DIM / KBLK)    // 8

typedef unsigned long long ull;
typedef unsigned int u32;

// ---- device scratch ----
__device__ float d_Aseg[NSEG * B_DIM * OUT_DIM];
__device__ float d_Bseg[NSEG * B_DIM * OUT_DIM];
// transposed fp16 weights: [o][k]
__device__ __half d_wg[OUT_DIM * INP_DIM];
__device__ __half d_wh[OUT_DIM * INP_DIM];
// precomputed time gate rt[t][o] = 2*sigmoid(t/T * r[o] + rb[o])
__device__ float d_rt[T_TOTAL * OUT_DIM];

// ---- smem layout (bytes) ----
#define SOFF_BIAS 0                     // gb,hb floats [2][128] = 1024
#define SOFF_QA   2048                  // [2][128] floats
#define SOFF_QB   3072
#define SOFF_STA  4096                  // [128] floats
#define SOFF_STB  4608
#define SOFF_BUF0 8192                  // two 40KB staging buffers
#define BUF_X     0                     // 64t x 64k fp16 = 8KB (SW128)
#define BUF_WG    8192                  // 128o x 64k fp16 = 16KB
#define BUF_WH    24576                 // 16KB
#define BUF_BYTES 40960
#define SOFF_GA   8192                  // alias: [64][128] float = 32KB (G gate)
#define SOFF_GB   40960                 // alias: [64][128] float = 32KB (H gate)
#define SMEM_BYTES (SOFF_BUF0 + 2 * BUF_BYTES)   // 90112  (x2 CTAs = 176KB/SM)

// ---- helpers ----
__device__ __forceinline__ u32 smem_u32(const void* p) {
    u32 a;
    asm("{ .reg .u64 t; cvta.to.shared.u64 t, %1; cvt.u32.u64 %0, t; }" : "=r"(a) : "l"(p));
    return a;
}
__device__ __forceinline__ void ldsm_x4(u32* r, u32 addr) {
    asm volatile("ldmatrix.sync.aligned.m8n8.x4.shared.b16 {%0,%1,%2,%3}, [%4];"
        : "=r"(r[0]), "=r"(r[1]), "=r"(r[2]), "=r"(r[3]) : "r"(addr));
}
__device__ __forceinline__ void mma16816(float* d, const u32* a, const u32* b) {
    asm volatile("mma.sync.aligned.m16n8k16.row.col.f32.f16.f16.f32 "
                 "{%0,%1,%2,%3}, {%4,%5,%6,%7}, {%8,%9}, {%0,%1,%2,%3};"
        : "+f"(d[0]), "+f"(d[1]), "+f"(d[2]), "+f"(d[3])
        : "r"(a[0]), "r"(a[1]), "r"(a[2]), "r"(a[3]), "r"(b[0]), "r"(b[1]));
}
__device__ __forceinline__ void cp_async16(u32 saddr, const void* gaddr) {
    asm volatile("cp.async.cg.shared.global [%0], [%1], 16;" :: "r"(saddr), "l"(gaddr));
}
#define CP_COMMIT()  asm volatile("cp.async.commit_group;" ::: "memory")
#define CP_WAIT0()   asm volatile("cp.async.wait_group 0;" ::: "memory")

__device__ __forceinline__ float sigf(float x)  { return 1.0f / (1.0f + __expf(-x)); }
__device__ __forceinline__ float tanhf_(float x){ return 2.0f / (1.0f + __expf(-2.0f * x)) - 1.0f; }

// ---------------- weight prep: tiled transpose fp32[k][o] -> fp16[o][k] ----------------
__global__ void wprep_kernel(const float* __restrict__ g, const float* __restrict__ h)
{
    __shared__ float tg[32][33], th[32][33];
    const int k0 = blockIdx.y * 32, o0 = blockIdx.x * 32;
    const int tx = threadIdx.x, ty = threadIdx.y;
    tg[ty][tx] = g[(size_t)(k0 + ty) * OUT_DIM + o0 + tx];
    th[ty][tx] = h[(size_t)(k0 + ty) * OUT_DIM + o0 + tx];
    __syncthreads();
    d_wg[(size_t)(o0 + ty) * INP_DIM + k0 + tx] = __float2half_rn(tg[tx][ty]);
    d_wh[(size_t)(o0 + ty) * INP_DIM + k0 + tx] = __float2half_rn(th[tx][ty]);
}

// ---------------- rt prep: rt[t][o] = 2*sigmoid(t/T * r[o] + rb[o]) ----------------
__global__ void rtprep_kernel(const float* __restrict__ r, const float* __restrict__ rb)
{
    const int idx = blockIdx.x * 256 + threadIdx.x;   // over T_TOTAL*OUT_DIM
    const int t = idx >> 9, o = idx & 511;
    const float tn = (float)t * (1.0f / (float)T_TOTAL);
    d_rt[idx] = 2.0f * sigf(fmaf(tn, r[o], rb[o]));
}

// ---------------- main fused kernel ----------------
// Grid: (4, 64, 8) = 2048 blocks, 256 threads (8 warps), 2 CTAs/SM.
// Warp w: gate = w>>2 (0:G, 1:H), oq = w&3 (32-o chunk).
// Per-warp tile: 64t x 32o, one gate, fp16 mma m16n8k16 (acc 4mt x 4nt x 4).
__global__ __launch_bounds__(256, 2)
void rnn_mma_kernel(const float* __restrict__ x,
                    const float* __restrict__ gb, const float* __restrict__ hb)
{
    extern __shared__ char smem[];
    const u32 sb   = smem_u32(smem);
    const int tid  = threadIdx.x;
    const int lane = tid & 31;
    const int w    = tid >> 5;
    const int oq   = w & 3;
    const int gate = w >> 2;
    const int s    = blockIdx.z;
    const int b    = blockIdx.y;
    const int o0   = blockIdx.x * OTILE;

    float* biasG  = (float*)(smem + SOFF_BIAS);
    float* biasH  = biasG + 128;
    float* qA     = (float*)(smem + SOFF_QA);
    float* qB     = (float*)(smem + SOFF_QB);
    float* stateA = (float*)(smem + SOFF_STA);
    float* stateB = (float*)(smem + SOFF_STB);

    if (tid < 128) {
        biasG[tid]  = gb[o0 + tid];
        biasH[tid]  = hb[o0 + tid];
        stateA[tid] = 1.0f;
        stateB[tid] = 0.0f;
    }

    // ---- staging helpers ----
    auto ldg_x = [&](float4* xr, int t0, int k0) {
        #pragma unroll
        for (int it = 0; it < 4; it++) {
            int q  = tid + 256 * it;
            int m  = q >> 4;
            int f4 = q & 15;
            xr[it] = *(const float4*)&x[((size_t)(t0 + m) * B_DIM + b) * INP_DIM + k0 + f4 * 4];
        }
    };
    auto sts_x = [&](u32 bufoff, const float4* xr) {
        #pragma unroll
        for (int it = 0; it < 4; it++) {
            int q  = tid + 256 * it;
            int m  = q >> 4;
            int f4 = q & 15;
            __half2 p0 = __floats2half2_rn(xr[it].x, xr[it].y);
            __half2 p1 = __floats2half2_rn(xr[it].z, xr[it].w);
            u32 off = (u32)m * 128 + (u32)f4 * 8;
            u32 sw  = off ^ (((u32)(m & 7)) << 4);
            ull d = (ull)*(const u32*)&p0 | ((ull)*(const u32*)&p1 << 32);
            *(ull*)(smem + bufoff + BUF_X + sw) = d;
        }
    };
    auto stage_w = [&](u32 bufoff, int k0) {
        #pragma unroll
        for (int it = 0; it < 4; it++) {
            int q   = tid + 256 * it;        // 0..1023 16B chunks per gate
            int row = q >> 3;
            int u4  = q & 7;
            u32 off = (u32)row * 128 + (u32)u4 * 16;
            u32 sw  = off ^ (((u32)(row & 7)) << 4);
            const size_t gidx = (size_t)(o0 + row) * INP_DIM + k0 + u4 * 8;
            cp_async16(sb + bufoff + BUF_WG + sw, &d_wg[gidx]);
            cp_async16(sb + bufoff + BUF_WH + sw, &d_wh[gidx]);
        }
    };

    // ldmatrix per-lane address pieces
    const int rowA  = lane & 15;                                   // + mt*16
    const u32 aXor  = ((u32)(rowA & 7)) << 4;
    const u32 aC0   = ((u32)(lane >> 4)) << 4;
    const int rowB0 = oq * 32 + (lane & 7) + ((lane >> 4) << 3);   // x4: two n8 tiles
    const u32 bC0   = ((u32)((lane >> 3) & 1)) << 4;
    const u32 wSel  = gate ? BUF_WH : BUF_WG;

    // prefetch sub 0's first x slice
    float4 xr[4];
    ldg_x(xr, s * SEG_LEN, 0);

    for (int sub = 0; sub < NSUB; sub++) {
        const int t0 = s * SEG_LEN + sub * MTILE;

        float acc[4][4][4];
        #pragma unroll
        for (int mt = 0; mt < 4; mt++)
            #pragma unroll
            for (int nt = 0; nt < 4; nt++)
                #pragma unroll
                for (int e = 0; e < 4; e++) acc[mt][nt][e] = 0.0f;

        // ---- prologue: stage k-block 0 into buf0 (x already in regs) ----
        stage_w(SOFF_BUF0, 0);
        CP_COMMIT();
        sts_x(SOFF_BUF0, xr);

        u32 buf = SOFF_BUF0;
        for (int kb = 0; kb < NKBLK; kb++) {
            const u32 nbuf = SOFF_BUF0 + (BUF_BYTES ^ (buf - SOFF_BUF0));
            const bool more = (kb + 1 < NKBLK);

            if (more) ldg_x(xr, t0, (kb + 1) * KBLK);   // LDG rides under wait+compute
            CP_WAIT0();
            __syncthreads();              // buf fully staged; prior compute done
            if (more) { stage_w(nbuf, (kb + 1) * KBLK); CP_COMMIT(); }  // overlaps mmas

            // ---- compute: 4 k16 steps on `buf` ----
            const u32 aBase = sb + buf + BUF_X + (u32)rowA * 128;
            const u32 wBase = sb + buf + wSel;
            #pragma unroll
            for (int ks = 0; ks < 4; ks++) {
                u32 a[4][4];
                const u32 c = (aC0 + (u32)ks * 32) ^ aXor;
                #pragma unroll
                for (int mt = 0; mt < 4; mt++)
                    ldsm_x4(a[mt], aBase + (u32)mt * 2048 + c);
                #pragma unroll
                for (int np = 0; np < 2; np++) {
                    const int rowB = rowB0 + np * 16;
                    const u32 boff = (u32)rowB * 128 + ((bC0 + (u32)ks * 32) ^ (((u32)(rowB & 7)) << 4));
                    u32 bf[4];
                    ldsm_x4(bf, wBase + boff);      // two n8 tiles
                    #pragma unroll
                    for (int mt = 0; mt < 4; mt++) {
                        mma16816(acc[mt][np * 2 + 0], a[mt], bf + 0);
                        mma16816(acc[mt][np * 2 + 1], a[mt], bf + 2);
                    }
                }
            }
            if (more) sts_x(nbuf, xr);    // LDG data has landed during compute
            buf = nbuf;
        }

        // prefetch next sub's first x slice; LDG latency hides under epilogue+scan
        if (sub + 1 < NSUB) ldg_x(xr, t0 + MTILE, 0);

        __syncthreads();                  // all compute done; GA/GB may alias buffers

        // ---- epilogue: activations (rt from table) -> smem [64t][128o] ----
        {
            float* dst = (float*)(smem + (gate ? SOFF_GB : SOFF_GA));
            const float* rtp = d_rt + (size_t)t0 * OUT_DIM + o0;
            #pragma unroll
            for (int mt = 0; mt < 4; mt++)
                #pragma unroll
                for (int np = 0; np < 2; np++)
                    #pragma unroll
                    for (int j = 0; j < 2; j++)
                        #pragma unroll
                        for (int e = 0; e < 4; e++) {
                            const int tl = mt * 16 + (lane >> 2) + ((e >> 1) * 8);
                            const int oo = oq * 32 + np * 16 + j * 8 + (lane & 3) * 2 + (e & 1);
                            const float rt = rtp[(size_t)tl * OUT_DIM + oo];
                            const float v  = acc[mt][np * 2 + j][e];
                            dst[tl * 128 + oo] = gate ? (tanhf_(v + biasH[oo]) * rt)
                                                      : (sigf (v + biasG[oo]) * rt);
                        }
        }
        __syncthreads();

        // ---- scan: 2 half-spans of 32 t each, per o ----
        {
            const int oo = tid & 127, qt = tid >> 7;   // qt in {0,1}
            const float* GA = (const float*)(smem + SOFF_GA);
            const float* GB = (const float*)(smem + SOFF_GB);
            float A = 1.0f, Bv = 0.0f;
            #pragma unroll
            for (int i = 0; i < 32; i++) {
                const int tl = qt * 32 + i;
                const float a  = GA[tl * 128 + oo];
                const float bb = GB[tl * 128 + oo];
                Bv = fmaf(Bv, a, bb);
                A *= a;
            }
            qA[qt * 128 + oo] = A;
            qB[qt * 128 + oo] = Bv;
        }
        __syncthreads();

        if (tid < 128) {
            float As = stateA[tid], Bs = stateB[tid];
            #pragma unroll
            for (int qt = 0; qt < 2; qt++) {
                const float a  = qA[qt * 128 + tid];
                const float bb = qB[qt * 128 + tid];
                Bs = fmaf(Bs, a, bb);
                As *= a;
            }
            stateA[tid] = As;
            stateB[tid] = Bs;
        }
        __syncthreads();   // state/scan reads done before next sub's staging overwrites
    }

    if (tid < 128) {
        const size_t idx = ((size_t)s * B_DIM + b) * OUT_DIM + o0 + tid;
        d_Aseg[idx] = stateA[tid];
        d_Bseg[idx] = stateB[tid];
    }
}

// ---------------- final combine over segments ----------------
__global__ void rnn_combine_kernel(float* __restrict__ out)
{
    const int idx = blockIdx.x * blockDim.x + threadIdx.x;
    float y = 0.0f;
    #pragma unroll
    for (int s = 0; s < NSEG; s++) {
        const float A = d_Aseg[s * B_DIM * OUT_DIM + idx];
        const float B = d_Bseg[s * B_DIM * OUT_DIM + idx];
        y = fmaf(y, A, B);
    }
    out[idx] = y;
}

extern "C" void kernel_launch(void* const* d_in, const int* in_sizes, int n_in,
                              void* d_out, int out_size)
{
    const float* x  = (const float*)d_in[0];
    const float* g  = (const float*)d_in[1];
    const float* gb = (const float*)d_in[2];
    const float* h  = (const float*)d_in[3];
    const float* hb = (const float*)d_in[4];
    const float* r  = (const float*)d_in[5];
    const float* rb = (const float*)d_in[6];
    float* out = (float*)d_out;

    cudaFuncSetAttribute(rnn_mma_kernel, cudaFuncAttributeMaxDynamicSharedMemorySize, SMEM_BYTES);

    dim3 pgrid(OUT_DIM / 32, INP_DIM / 32);
    wprep_kernel<<<pgrid, dim3(32, 32)>>>(g, h);
    rtprep_kernel<<<(T_TOTAL * OUT_DIM) / 256, 256>>>(r, rb);
    dim3 grid(OUT_DIM / OTILE, B_DIM, NSEG);   // (4, 64, 8)
    rnn_mma_kernel<<<grid, 256, SMEM_BYTES>>>(x, gb, hb);
    rnn_combine_kernel<<<(B_DIM * OUT_DIM) / 512, 512>>>(out);
}

// round 15
// speedup vs baseline: 2.4540x; 1.3861x over previous
#include <cuda_runtime.h>
#include <cuda_fp16.h>
#include <cstdint>

#define T_TOTAL 2048
#define B_DIM   64
#define INP_DIM 512
#define OUT_DIM 512

#define NSEG    8
#define SEG_LEN 256                 // T per segment
#define MTILE   64                  // t rows per block tile
#define NSUB    (SEG_LEN / MTILE)   // 4
#define OTILE   128                 // o cols per block
#define KBLK    64                  // K per staged slice
#define NKBLK   (INP_DIM / KBLK)    // 8

#define GROW    136                 // padded G/H row stride in floats (bank-conflict-free)

typedef unsigned long long ull;
typedef unsigned int u32;

// ---- device scratch ----
__device__ float d_Aseg[NSEG * B_DIM * OUT_DIM];
__device__ float d_Bseg[NSEG * B_DIM * OUT_DIM];
__device__ __half d_wg[OUT_DIM * INP_DIM];   // transposed fp16 weights [o][k]
__device__ __half d_wh[OUT_DIM * INP_DIM];
__device__ float d_rt[T_TOTAL * OUT_DIM];    // rt[t][o] = 2*sigmoid(t/T*r[o]+rb[o])

// ---- smem layout (bytes) ----
#define SOFF_BIAS 0                     // gbh floats [2][128] = 1024
#define SOFF_QA   1024                  // [4][64] float2 = 2048
#define SOFF_QB   3072                  // 2048
#define SOFF_STA  5120                  // [128] floats
#define SOFF_STB  5632
#define SOFF_BUF0 8192                  // two 40KB staging buffers
#define BUF_X     0                     // 64t x 64k fp16 = 8KB (SW128)
#define BUF_WG    8192                  // 128o x 64k fp16 = 16KB
#define BUF_WH    24576                 // 16KB
#define BUF_BYTES 40960
#define SOFF_GA   8192                  // alias: [64][GROW] float = 34816B (G gate)
#define SOFF_GB   43008                 // alias: [64][GROW] float = 34816B (H gate)
#define SMEM_BYTES (SOFF_BUF0 + 2 * BUF_BYTES)   // 90112  (x2 CTAs = 176KB/SM)

// ---- helpers ----
__device__ __forceinline__ u32 smem_u32(const void* p) {
    u32 a;
    asm("{ .reg .u64 t; cvta.to.shared.u64 t, %1; cvt.u32.u64 %0, t; }" : "=r"(a) : "l"(p));
    return a;
}
__device__ __forceinline__ void ldsm_x4(u32* r, u32 addr) {
    asm volatile("ldmatrix.sync.aligned.m8n8.x4.shared.b16 {%0,%1,%2,%3}, [%4];"
        : "=r"(r[0]), "=r"(r[1]), "=r"(r[2]), "=r"(r[3]) : "r"(addr));
}
__device__ __forceinline__ void mma16816(float* d, const u32* a, const u32* b) {
    asm volatile("mma.sync.aligned.m16n8k16.row.col.f32.f16.f16.f32 "
                 "{%0,%1,%2,%3}, {%4,%5,%6,%7}, {%8,%9}, {%0,%1,%2,%3};"
        : "+f"(d[0]), "+f"(d[1]), "+f"(d[2]), "+f"(d[3])
        : "r"(a[0]), "r"(a[1]), "r"(a[2]), "r"(a[3]), "r"(b[0]), "r"(b[1]));
}
__device__ __forceinline__ void cp_async16(u32 saddr, const void* gaddr) {
    asm volatile("cp.async.cg.shared.global [%0], [%1], 16;" :: "r"(saddr), "l"(gaddr));
}
#define CP_COMMIT()  asm volatile("cp.async.commit_group;" ::: "memory")
#define CP_WAIT0()   asm volatile("cp.async.wait_group 0;" ::: "memory")

__device__ __forceinline__ float sigf(float x)  { return 1.0f / (1.0f + __expf(-x)); }
__device__ __forceinline__ float tanha(float x) {
    float y; asm("tanh.approx.f32 %0, %1;" : "=f"(y) : "f"(x)); return y;
}

// ---------------- weight prep: tiled transpose fp32[k][o] -> fp16[o][k] ----------------
__global__ void wprep_kernel(const float* __restrict__ g, const float* __restrict__ h)
{
    __shared__ float tg[32][33], th[32][33];
    const int k0 = blockIdx.y * 32, o0 = blockIdx.x * 32;
    const int tx = threadIdx.x, ty = threadIdx.y;
    tg[ty][tx] = g[(size_t)(k0 + ty) * OUT_DIM + o0 + tx];
    th[ty][tx] = h[(size_t)(k0 + ty) * OUT_DIM + o0 + tx];
    __syncthreads();
    d_wg[(size_t)(o0 + ty) * INP_DIM + k0 + tx] = __float2half_rn(tg[tx][ty]);
    d_wh[(size_t)(o0 + ty) * INP_DIM + k0 + tx] = __float2half_rn(th[tx][ty]);
}

// ---------------- rt prep (fp32 exact, same formula as reference) ----------------
__global__ void rtprep_kernel(const float* __restrict__ r, const float* __restrict__ rb)
{
    const int idx = blockIdx.x * 256 + threadIdx.x;
    const int t = idx >> 9, o = idx & 511;
    const float tn = (float)t * (1.0f / (float)T_TOTAL);
    d_rt[idx] = 2.0f * sigf(fmaf(tn, r[o], rb[o]));
}

// ---------------- main fused kernel ----------------
// Grid: (4, 64, 8), 256 threads (8 warps), 2 CTAs/SM.
// Warp w: gate = w>>2 (0:G, 1:H), oq = w&3 (32-o chunk). Warp tile 64t x 32o.
__global__ __launch_bounds__(256, 2)
void rnn_mma_kernel(const float* __restrict__ x,
                    const float* __restrict__ gb, const float* __restrict__ hb)
{
    extern __shared__ char smem[];
    const u32 sb   = smem_u32(smem);
    const int tid  = threadIdx.x;
    const int lane = tid & 31;
    const int w    = tid >> 5;
    const int oq   = w & 3;
    const int gate = w >> 2;
    const int s    = blockIdx.z;
    const int b    = blockIdx.y;
    const int o0   = blockIdx.x * OTILE;

    float* biasGH = (float*)(smem + SOFF_BIAS);   // 0.5*gb | hb
    float* stateA = (float*)(smem + SOFF_STA);
    float* stateB = (float*)(smem + SOFF_STB);

    if (tid < 128) {
        biasGH[tid]       = 0.5f * gb[o0 + tid];  // pre-halved for tanh identity
        biasGH[128 + tid] = hb[o0 + tid];
        stateA[tid] = 1.0f;
        stateB[tid] = 0.0f;
    }

    // ---- staging helpers ----
    auto ldg_x = [&](float4* xr, int t0, int k0) {
        #pragma unroll
        for (int it = 0; it < 4; it++) {
            int q  = tid + 256 * it;
            int m  = q >> 4;
            int f4 = q & 15;
            xr[it] = *(const float4*)&x[((size_t)(t0 + m) * B_DIM + b) * INP_DIM + k0 + f4 * 4];
        }
    };
    auto sts_x = [&](u32 bufoff, const float4* xr) {
        #pragma unroll
        for (int it = 0; it < 4; it++) {
            int q  = tid + 256 * it;
            int m  = q >> 4;
            int f4 = q & 15;
            __half2 p0 = __floats2half2_rn(xr[it].x, xr[it].y);
            __half2 p1 = __floats2half2_rn(xr[it].z, xr[it].w);
            u32 off = (u32)m * 128 + (u32)f4 * 8;
            u32 sw  = off ^ (((u32)(m & 7)) << 4);
            ull d = (ull)*(const u32*)&p0 | ((ull)*(const u32*)&p1 << 32);
            *(ull*)(smem + bufoff + BUF_X + sw) = d;
        }
    };
    auto stage_w = [&](u32 bufoff, int k0) {
        #pragma unroll
        for (int it = 0; it < 4; it++) {
            int q   = tid + 256 * it;
            int row = q >> 3;
            int u4  = q & 7;
            u32 off = (u32)row * 128 + (u32)u4 * 16;
            u32 sw  = off ^ (((u32)(row & 7)) << 4);
            const size_t gidx = (size_t)(o0 + row) * INP_DIM + k0 + u4 * 8;
            cp_async16(sb + bufoff + BUF_WG + sw, &d_wg[gidx]);
            cp_async16(sb + bufoff + BUF_WH + sw, &d_wh[gidx]);
        }
    };

    // ldmatrix per-lane address pieces
    const int rowA  = lane & 15;
    const u32 aXor  = ((u32)(rowA & 7)) << 4;
    const u32 aC0   = ((u32)(lane >> 4)) << 4;
    const int rowB0 = oq * 32 + (lane & 7) + ((lane >> 4) << 3);
    const u32 bC0   = ((u32)((lane >> 3) & 1)) << 4;
    const u32 wSel  = gate ? BUF_WH : BUF_WG;

    // prefetch sub 0's first x slice
    float4 xr[4];
    ldg_x(xr, s * SEG_LEN, 0);

    for (int sub = 0; sub < NSUB; sub++) {
        const int t0 = s * SEG_LEN + sub * MTILE;

        float acc[4][4][4];
        #pragma unroll
        for (int mt = 0; mt < 4; mt++)
            #pragma unroll
            for (int nt = 0; nt < 4; nt++)
                #pragma unroll
                for (int e = 0; e < 4; e++) acc[mt][nt][e] = 0.0f;

        // ---- prologue ----
        stage_w(SOFF_BUF0, 0);
        CP_COMMIT();
        sts_x(SOFF_BUF0, xr);

        u32 buf = SOFF_BUF0;
        for (int kb = 0; kb < NKBLK; kb++) {
            const u32 nbuf = SOFF_BUF0 + (BUF_BYTES ^ (buf - SOFF_BUF0));
            const bool more = (kb + 1 < NKBLK);

            if (more) ldg_x(xr, t0, (kb + 1) * KBLK);
            CP_WAIT0();
            __syncthreads();
            if (more) { stage_w(nbuf, (kb + 1) * KBLK); CP_COMMIT(); }

            const u32 aBase = sb + buf + BUF_X + (u32)rowA * 128;
            const u32 wBase = sb + buf + wSel;
            #pragma unroll
            for (int ks = 0; ks < 4; ks++) {
                u32 a[4][4];
                const u32 c = (aC0 + (u32)ks * 32) ^ aXor;
                #pragma unroll
                for (int mt = 0; mt < 4; mt++)
                    ldsm_x4(a[mt], aBase + (u32)mt * 2048 + c);
                #pragma unroll
                for (int np = 0; np < 2; np++) {
                    const int rowB = rowB0 + np * 16;
                    const u32 boff = (u32)rowB * 128 + ((bC0 + (u32)ks * 32) ^ (((u32)(rowB & 7)) << 4));
                    u32 bf[4];
                    ldsm_x4(bf, wBase + boff);
                    #pragma unroll
                    for (int mt = 0; mt < 4; mt++) {
                        mma16816(acc[mt][np * 2 + 0], a[mt], bf + 0);
                        mma16816(acc[mt][np * 2 + 1], a[mt], bf + 2);
                    }
                }
            }
            if (more) sts_x(nbuf, xr);
            buf = nbuf;
        }

        // prefetch next sub's first x slice (hides under epilogue+scan)
        if (sub + 1 < NSUB) ldg_x(xr, t0 + MTILE, 0);

        __syncthreads();                  // compute done; GA/GB may alias buffers

        // ---- epilogue: activations via tanh.approx -> padded smem tile ----
        {
            float2* dst = (float2*)(smem + (gate ? SOFF_GB : SOFF_GA));
            const float* rtp = d_rt + (size_t)t0 * OUT_DIM + o0;
            #pragma unroll
            for (int mt = 0; mt < 4; mt++)
                #pragma unroll
                for (int np = 0; np < 2; np++)
                    #pragma unroll
                    for (int j = 0; j < 2; j++)
                        #pragma unroll
                        for (int e2 = 0; e2 < 2; e2++) {
                            const int tl = mt * 16 + (lane >> 2) + e2 * 8;
                            const int oo = oq * 32 + np * 16 + j * 8 + (lane & 3) * 2;
                            const float2 rt = *(const float2*)&rtp[(size_t)tl * OUT_DIM + oo];
                            const float v0 = acc[mt][np * 2 + j][e2 * 2 + 0];
                            const float v1 = acc[mt][np * 2 + j][e2 * 2 + 1];
                            float2 out;
                            if (gate) {   // H = tanh(v + hb) * rt
                                out.x = tanha(v0 + biasGH[128 + oo])     * rt.x;
                                out.y = tanha(v1 + biasGH[128 + oo + 1]) * rt.y;
                            } else {      // G = sig(v+gb)*rt = 0.5rt + 0.5rt*tanh(0.5v+0.5gb)
                                const float hrt0 = 0.5f * rt.x, hrt1 = 0.5f * rt.y;
                                out.x = fmaf(tanha(fmaf(0.5f, v0, biasGH[oo])),     hrt0, hrt0);
                                out.y = fmaf(tanha(fmaf(0.5f, v1, biasGH[oo + 1])), hrt1, hrt1);
                            }
                            dst[tl * (GROW / 2) + (oo >> 1)] = out;
                        }
        }
        __syncthreads();

        // ---- scan: 4 quarter-spans of 16 t, 64 o-pairs (float2) ----
        {
            const int op = tid & 63, qt = tid >> 6;
            const float2* GA = (const float2*)(smem + SOFF_GA);
            const float2* GB = (const float2*)(smem + SOFF_GB);
            float2* qA = (float2*)(smem + SOFF_QA);
            float2* qB = (float2*)(smem + SOFF_QB);
            float2 A = make_float2(1.0f, 1.0f), Bv = make_float2(0.0f, 0.0f);
            #pragma unroll
            for (int i = 0; i < 16; i++) {
                const int tl = qt * 16 + i;
                const float2 a  = GA[tl * (GROW / 2) + op];
                const float2 bb = GB[tl * (GROW / 2) + op];
                Bv.x = fmaf(Bv.x, a.x, bb.x);
                Bv.y = fmaf(Bv.y, a.y, bb.y);
                A.x *= a.x;
                A.y *= a.y;
            }
            qA[qt * 64 + op] = A;
            qB[qt * 64 + op] = Bv;
        }
        __syncthreads();

        if (tid < 128) {
            const float* qAf = (const float*)(smem + SOFF_QA);
            const float* qBf = (const float*)(smem + SOFF_QB);
            float As = stateA[tid], Bs = stateB[tid];
            #pragma unroll
            for (int qt = 0; qt < 4; qt++) {
                const float a  = qAf[qt * 128 + tid];
                const float bb = qBf[qt * 128 + tid];
                Bs = fmaf(Bs, a, bb);
                As *= a;
            }
            stateA[tid] = As;
            stateB[tid] = Bs;
        }
        __syncthreads();
    }

    if (tid < 128) {
        const size_t idx = ((size_t)s * B_DIM + b) * OUT_DIM + o0 + tid;
        d_Aseg[idx] = stateA[tid];
        d_Bseg[idx] = stateB[tid];
    }
}

// ---------------- final combine over segments ----------------
__global__ void rnn_combine_kernel(float* __restrict__ out)
{
    const int idx = blockIdx.x * blockDim.x + threadIdx.x;
    float y = 0.0f;
    #pragma unroll
    for (int s = 0; s < NSEG; s++) {
        const float A = d_Aseg[s * B_DIM * OUT_DIM + idx];
        const float B = d_Bseg[s * B_DIM * OUT_DIM + idx];
        y = fmaf(y, A, B);
    }
    out[idx] = y;
}

extern "C" void kernel_launch(void* const* d_in, const int* in_sizes, int n_in,
                              void* d_out, int out_size)
{
    const float* x  = (const float*)d_in[0];
    const float* g  = (const float*)d_in[1];
    const float* gb = (const float*)d_in[2];
    const float* h  = (const float*)d_in[3];
    const float* hb = (const float*)d_in[4];
    const float* r  = (const float*)d_in[5];
    const float* rb = (const float*)d_in[6];
    float* out = (float*)d_out;

    cudaFuncSetAttribute(rnn_mma_kernel, cudaFuncAttributeMaxDynamicSharedMemorySize, SMEM_BYTES);

    dim3 pgrid(OUT_DIM / 32, INP_DIM / 32);
    wprep_kernel<<<pgrid, dim3(32, 32)>>>(g, h);
    rtprep_kernel<<<(T_TOTAL * OUT_DIM) / 256, 256>>>(r, rb);
    dim3 grid(OUT_DIM / OTILE, B_DIM, NSEG);   // (4, 64, 8)
    rnn_mma_kernel<<<grid, 256, SMEM_BYTES>>>(x, gb, hb);
    rnn_combine_kernel<<<(B_DIM * OUT_DIM) / 512, 512>>>(out);
}